// round 12
// baseline (speedup 1.0000x reference)
#include <cuda_runtime.h>
#include <cuda_bf16.h>
#include <cstdint>
#include <cstddef>

// ---------------- problem constants ----------------
constexpr int N_  = 16;
constexpr int D_  = 16;
constexpr int S_  = 112;
constexpr int SS_ = S_ * S_;          // 12544
constexpr int M_  = 2;
constexpr int V_  = 7829;
constexpr int K_  = 512;
constexpr int NM_ = N_ * M_;          // 32
constexpr int NCH = 16;               // v-chunks
constexpr int VCH = (V_ + NCH - 1) / NCH;   // 490
constexpr int CAP = 32;               // candidate slots per (k, chunk)
constexpr int CYB = 16;               // k_cyc grid.y
constexpr float TSCALE = 20.0f;       // 1/T
constexpr float THRESH = -13.0f;      // keep 20*(sim - rmax) > -13 (dropped mass ~2e-6)
constexpr float SH     = 60.0f;       // fixed column-softmax shift (no cmax reduction needed)

// ---------------- static device scratch ----------------
__device__ __nv_bfloat16 g_bt[(size_t)NM_ * V_ * K_];   // [nm][v][k] B-tilde (bf16)
__device__ float g_sampled[N_ * K_ * D_];
__device__ float g_fx[N_ * K_], g_fy[N_ * K_];
__device__ float g_rpmax[NM_ * NCH * K_];
__device__ float g_rpsum[NM_ * NCH * K_];
__device__ float g_tk[NM_ * K_];                  // -20*rmax[k]
__device__ float g_rk[NM_ * K_];                  // 1/rsum[k]
__device__ int   g_cnt[NM_ * NCH * K_];
__device__ uint2 g_cand[(size_t)NM_ * NCH * K_ * CAP];   // {v, e=exp(20sim+tk)}
__device__ float g_partial[NM_ * CYB];
__device__ int   g_is64;

// ---------------- fast exp: pure FMA, branchless, ~1.3e-6 rel err ----------------
static __device__ __forceinline__ float fexp(float x) {
    float y = x * 1.4426950408889634f;           // x/ln2
    y = fminf(y, 126.0f);
    y = fmaxf(y, -127.0f);                        // underflow -> ~0
    float fl = floorf(y);
    float f  = y - fl;                            // [0,1)
    float p = 1.5252733804e-5f;
    p = fmaf(p, f, 1.5403530393e-4f);
    p = fmaf(p, f, 1.3333558146e-3f);
    p = fmaf(p, f, 9.6181291076e-3f);
    p = fmaf(p, f, 5.5504108664e-2f);
    p = fmaf(p, f, 2.4022650696e-1f);
    p = fmaf(p, f, 6.9314718056e-1f);
    p = fmaf(p, f, 1.0f);
    return __int_as_float(__float_as_int(p) + (((int)fl) << 23));
}

// 16-term dot of sampled row (regs) with mesh row (broadcast float4 loads)
static __device__ __forceinline__ float dot16(const float* sk, const float4* mb, int v) {
    float4 m0 = mb[v * 4 + 0], m1 = mb[v * 4 + 1];
    float4 m2 = mb[v * 4 + 2], m3 = mb[v * 4 + 3];
    float s;
    s =          sk[0]  * m0.x;     s = fmaf(sk[1],  m0.y, s);
    s = fmaf(sk[2],  m0.z, s);      s = fmaf(sk[3],  m0.w, s);
    s = fmaf(sk[4],  m1.x, s);      s = fmaf(sk[5],  m1.y, s);
    s = fmaf(sk[6],  m1.z, s);      s = fmaf(sk[7],  m1.w, s);
    s = fmaf(sk[8],  m2.x, s);      s = fmaf(sk[9],  m2.y, s);
    s = fmaf(sk[10], m2.z, s);      s = fmaf(sk[11], m2.w, s);
    s = fmaf(sk[12], m3.x, s);      s = fmaf(sk[13], m3.y, s);
    s = fmaf(sk[14], m3.z, s);      s = fmaf(sk[15], m3.w, s);
    return s;
}

// ---------------- K0: detect int64 vs int32 indices ----------------
__global__ void k_detect(const int* __restrict__ w) {
    __shared__ int s_allzero;
    if (threadIdx.x == 0) s_allzero = 1;
    __syncthreads();
    int nz = 0;
    for (int i = threadIdx.x * 2 + 1; i < N_ * K_; i += blockDim.x * 2)
        if (w[i] != 0) nz = 1;
    if (nz) atomicAnd(&s_allzero, 0);
    __syncthreads();
    if (threadIdx.x == 0) g_is64 = s_allzero;
}

// ---------------- K1: gather + normalize sampled embeddings ----------------
__global__ void k_sample(const float* __restrict__ pix, const void* __restrict__ idxraw) {
    int t = blockIdx.x * blockDim.x + threadIdx.x;
    if (t >= N_ * K_) return;
    long long idx;
    if (g_is64) idx = ((const long long*)idxraw)[t];
    else        idx = (long long)((const int*)idxraw)[t];
    int n = t / K_;
    int p = (int)idx;
    g_fx[t] = (float)(p / S_);
    g_fy[t] = (float)(p % S_);
    const float* base = pix + (size_t)n * D_ * SS_ + p;
    float v[16]; float ss = 0.f;
#pragma unroll
    for (int d = 0; d < 16; d++) { v[d] = base[(size_t)d * SS_]; ss = fmaf(v[d], v[d], ss); }
    float inv = 1.0f / fmaxf(sqrtf(ss), 1e-6f);
#pragma unroll
    for (int d = 0; d < 16; d++) g_sampled[t * 16 + d] = v[d] * inv;
}

// ---------------- K2: on-the-fly sim, per-chunk row max only (no sim store) ----------------
__global__ void __launch_bounds__(512) k_simmax(const float* __restrict__ mesh) {
    int nm = blockIdx.x, ch = blockIdx.y;
    int k  = threadIdx.x;
    int n = nm / M_, m = nm % M_;
    float sk[16];
    const float* sp = &g_sampled[(n * K_ + k) * 16];
#pragma unroll
    for (int d = 0; d < 16; d++) sk[d] = sp[d];
    int v0 = ch * VCH;
    int v1 = min(v0 + VCH, V_);
    const float4* mb = (const float4*)(mesh + (size_t)m * V_ * D_);
    float mx = -1e30f;
#pragma unroll 2
    for (int v = v0; v < v1; v++)
        mx = fmaxf(mx, dot16(sk, mb, v));
    g_rpmax[(nm * NCH + ch) * K_ + k] = mx;
}

// ---------------- K2b: combine chunk maxes -> tk ----------------
__global__ void k_rowmax() {
    int t = blockIdx.x * blockDim.x + threadIdx.x;
    if (t >= NM_ * K_) return;
    int nm = t / K_, k = t % K_;
    float mx = -1e30f;
#pragma unroll
    for (int c = 0; c < NCH; c++) mx = fmaxf(mx, g_rpmax[(nm * NCH + c) * K_ + k]);
    g_tk[t] = -TSCALE * mx;
}

// ---------------- K3: fused recompute + column softmax (fixed shift) + B-tilde
//                      + candidate lists + row sums ----------------
// Block (nm, ch): 512 threads = full k-row per v. One __syncthreads per v
// (parity double-buffered cross-warp sum). Column softmax uses fixed shift SH:
//   e' = exp(20*s - SH); B[v][k] = e'/sum_k e'   (exactly the softmax ratio).
__global__ void __launch_bounds__(512) k_fuse(const float* __restrict__ mesh) {
    __shared__ float swarp[2][16];
    int nm = blockIdx.x, ch = blockIdx.y;
    int k  = threadIdx.x;
    int n = nm / M_, m = nm % M_;
    int wid = k >> 5, lane = k & 31;
    float sk[16];
    const float* sp = &g_sampled[(n * K_ + k) * 16];
#pragma unroll
    for (int d = 0; d < 16; d++) sk[d] = sp[d];
    float tk = g_tk[nm * K_ + k];
    int v0 = ch * VCH;
    int v1 = min(v0 + VCH, V_);
    const float4* mb = (const float4*)(mesh + (size_t)m * V_ * D_);
    uint2* cl = g_cand + ((size_t)((nm * NCH + ch) * K_ + k)) * CAP;
    __nv_bfloat16* bbase = g_bt + (size_t)nm * V_ * K_ + k;
    int cnt = 0; float rs = 0.f;

    for (int v = v0; v < v1; v++) {
        float s = dot16(sk, mb, v);
        float e = fexp(fmaf(TSCALE, s, -SH));
        // warp sum
        float ws = e;
#pragma unroll
        for (int o = 16; o > 0; o >>= 1) ws += __shfl_xor_sync(0xffffffffu, ws, o);
        int pb = v & 1;
        if (lane == 0) swarp[pb][wid] = ws;
        __syncthreads();
        // cross-warp sum (redundant in every warp; 16 values)
        float tt = (lane < 16) ? swarp[pb][lane] : 0.f;
#pragma unroll
        for (int o = 8; o > 0; o >>= 1) tt += __shfl_xor_sync(0xffffffffu, tt, o);
        float csum = __shfl_sync(0xffffffffu, tt, 0);
        bbase[(size_t)v * K_] = __float2bfloat16(__fdividef(e, csum));
        // candidate test (row softmax support)
        float t = fmaf(TSCALE, s, tk);
        if (t > THRESH) {
            float er = fexp(t);
            rs += er;
            if (cnt < CAP) cl[cnt] = make_uint2((unsigned)v, __float_as_uint(er));
            cnt++;
        }
    }
    g_cnt[(nm * NCH + ch) * K_ + k] = min(cnt, CAP);
    g_rpsum[(nm * NCH + ch) * K_ + k] = rs;
}

// ---------------- K3b: finalize rows -> rk ----------------
__global__ void k_rowfin() {
    int t = blockIdx.x * blockDim.x + threadIdx.x;
    if (t >= NM_ * K_) return;
    int nm = t / K_, k = t % K_;
    float s = 0.f;
#pragma unroll
    for (int c = 0; c < NCH; c++) s += g_rpsum[(nm * NCH + c) * K_ + k];
    g_rk[t] = 1.0f / s;
}

// ---------------- K5: sparse cycle (pure FMA) + fused loss ----------------
// Warp handles 4 k's; for each candidate v of row k:
//   C[k, q] += A[k,v] * B[v, q]   for all 512 q (16 per lane, from 8 bf16x2 words)
// then part += (dist2[k,q] * C)^2.
__global__ void __launch_bounds__(256) k_cyc() {
    __shared__ float sfx[K_], sfy[K_];
    __shared__ float red[256];
    int nm = blockIdx.x, by = blockIdx.y;
    int n = nm / M_;
    int tid = threadIdx.x, w = tid >> 5, lane = tid & 31;
    for (int i = tid; i < K_; i += 256) {
        sfx[i] = g_fx[n * K_ + i];
        sfy[i] = g_fy[n * K_ + i];
    }
    __syncthreads();

    float part = 0.f;
#pragma unroll 1
    for (int i = 0; i < 4; i++) {
        int k = by * 32 + w * 4 + i;
        float rkk = g_rk[nm * K_ + k];
        float acc[16];
#pragma unroll
        for (int j = 0; j < 16; j++) acc[j] = 0.f;

        for (int ch = 0; ch < NCH; ch++) {
            int base = (nm * NCH + ch) * K_ + k;
            int cnt = g_cnt[base];
            const uint2* cl = g_cand + (size_t)base * CAP;
            for (int c = 0; c < cnt; c++) {
                uint2 ce = cl[c];                        // broadcast load
                float wv = __uint_as_float(ce.y) * rkk;  // A[k,v]
                const uint32_t* row =
                    (const uint32_t*)(g_bt + ((size_t)nm * V_ + ce.x) * K_);
                uint32_t rw[8];
#pragma unroll
                for (int j = 0; j < 8; j++) rw[j] = __ldg(&row[j * 32 + lane]);
#pragma unroll
                for (int j = 0; j < 8; j++) {
                    float2 f = __bfloat1622float2(*reinterpret_cast<__nv_bfloat162*>(&rw[j]));
                    acc[2 * j]     = fmaf(wv, f.x, acc[2 * j]);
                    acc[2 * j + 1] = fmaf(wv, f.y, acc[2 * j + 1]);
                }
            }
        }

        float xk = sfx[k], yk = sfy[k];
#pragma unroll
        for (int j = 0; j < 8; j++) {
            int q0 = 2 * (j * 32 + lane);
            float dx0 = xk - sfx[q0], dy0 = yk - sfy[q0];
            float dist0 = fmaf(dx0, dx0, dy0 * dy0);
            float wt0 = dist0 * acc[2 * j];
            part = fmaf(wt0, wt0, part);
            float dx1 = xk - sfx[q0 + 1], dy1 = yk - sfy[q0 + 1];
            float dist1 = fmaf(dx1, dx1, dy1 * dy1);
            float wt1 = dist1 * acc[2 * j + 1];
            part = fmaf(wt1, wt1, part);
        }
    }
    red[tid] = part;
    __syncthreads();
    for (int o = 128; o > 0; o >>= 1) {
        if (tid < o) red[tid] += red[tid + o];
        __syncthreads();
    }
    if (tid == 0) g_partial[nm * CYB + by] = red[0];
}

// ---------------- K6: final sqrt + mean ----------------
__global__ void k_final(float* __restrict__ out) {
    int t = threadIdx.x;           // 32 threads, one per nm
    float s = 0.f;
#pragma unroll
    for (int pr = 0; pr < CYB; pr++) s += g_partial[t * CYB + pr];
    float l = sqrtf(s);
#pragma unroll
    for (int o = 16; o > 0; o >>= 1) l += __shfl_xor_sync(0xffffffffu, l, o);
    if (t == 0) out[0] = l / (float)NM_;
}

// ---------------- launch ----------------
extern "C" void kernel_launch(void* const* d_in, const int* in_sizes, int n_in,
                              void* d_out, int out_size) {
    const float* pix  = (const float*)d_in[0];
    const float* mesh = (const float*)d_in[1];
    const void*  idx  = d_in[2];
    float* out = (float*)d_out;
    (void)in_sizes; (void)n_in; (void)out_size;

    k_detect<<<1, 256>>>((const int*)idx);
    k_sample<<<(N_ * K_ + 255) / 256, 256>>>(pix, idx);
    k_simmax<<<dim3(NM_, NCH), 512>>>(mesh);
    k_rowmax<<<(NM_ * K_ + 255) / 256, 256>>>();
    k_fuse<<<dim3(NM_, NCH), 512>>>(mesh);
    k_rowfin<<<(NM_ * K_ + 255) / 256, 256>>>();
    k_cyc<<<dim3(NM_, CYB), 256>>>();
    k_final<<<1, 32>>>(out);
}